// round 16
// baseline (speedup 1.0000x reference)
#include <cuda_runtime.h>
#include <cuda_bf16.h>
#include <math.h>

// Problem constants
#define BATCH 4
#define SEQ 2048
#define DMODEL 512
#define NHEADS 8
#define DK 64
#define MROWS (BATCH * SEQ)   // 8192

// ---------------- scratch (static device globals; no allocation allowed) ---------
// Referenced ONLY from device code (round-2/4 lesson).
// All tensor-op operand buffers hold tf32-RNA-rounded fp32 so raw loads feed
// mma.sync exactly (truncation of already-rounded values is a no-op — r14 proof).
__device__ float g_Q[BATCH * NHEADS * SEQ * DK];    // head-major [B,H,N,64]
__device__ float g_K[BATCH * NHEADS * SEQ * DK];
__device__ float g_V[BATCH * NHEADS * SEQ * DK];
__device__ float g_attn[MROWS * DMODEL];            // flat [8192,512], rounded
__device__ float g_Xr[MROWS * DMODEL];              // rna(x)
__device__ float g_WT[4 * DMODEL * DMODEL];         // rna(W^T): Wq,Wk,Wv,Wo K-major

// ---------------- helpers ---------------------------------------------------------
__device__ __forceinline__ unsigned f2tf32(float x) {
    unsigned u;
    asm("cvt.rna.tf32.f32 %0, %1;" : "=r"(u) : "f"(x));
    return u;
}
__device__ __forceinline__ float f2tf32f(float x) {
    unsigned u;
    asm("cvt.rna.tf32.f32 %0, %1;" : "=r"(u) : "f"(x));
    return __uint_as_float(u);
}
__device__ __forceinline__ void mma_tf32(float* c, const unsigned* a, unsigned b0, unsigned b1) {
    asm volatile(
        "mma.sync.aligned.m16n8k8.row.col.f32.tf32.tf32.f32 "
        "{%0,%1,%2,%3}, {%4,%5,%6,%7}, {%8,%9}, {%0,%1,%2,%3};"
        : "+f"(c[0]), "+f"(c[1]), "+f"(c[2]), "+f"(c[3])
        : "r"(a[0]), "r"(a[1]), "r"(a[2]), "r"(a[3]), "r"(b0), "r"(b1));
}
__device__ __forceinline__ void cp_async16(unsigned smem_addr, const void* gptr) {
    asm volatile("cp.async.cg.shared.global [%0], [%1], 16;" :: "r"(smem_addr), "l"(gptr));
}
__device__ __forceinline__ void cp_async_commit()   { asm volatile("cp.async.commit_group;"); }
__device__ __forceinline__ void cp_async_wait_all() { asm volatile("cp.async.wait_group 0;"); }

__device__ __forceinline__ unsigned smem_u32(const void* p) {
    unsigned a;
    asm("{ .reg .u64 t; cvta.to.shared.u64 t, %1; cvt.u32.u64 %0, t; }" : "=r"(a) : "l"(p));
    return a;
}

// =================================================================================
// Pre-passes: RNA-round x; transpose+round the four weights into g_WT (K-major).
// =================================================================================
__global__ void __launch_bounds__(256)
round_x_kernel(const float* __restrict__ x)
{
    const int i = blockIdx.x * 256 + threadIdx.x;   // 1,048,576 float4
    float4 v = reinterpret_cast<const float4*>(x)[i];
    v.x = f2tf32f(v.x); v.y = f2tf32f(v.y); v.z = f2tf32f(v.z); v.w = f2tf32f(v.w);
    reinterpret_cast<float4*>(g_Xr)[i] = v;
}

__global__ void __launch_bounds__(256)
transpose_round_kernel(const float* __restrict__ Wq, const float* __restrict__ Wk,
                       const float* __restrict__ Wv, const float* __restrict__ Wo)
{
    __shared__ float t[32][33];
    const int z = blockIdx.z;
    const float* W = (z == 0) ? Wq : (z == 1) ? Wk : (z == 2) ? Wv : Wo;
    float* out = g_WT + (size_t)z * DMODEL * DMODEL;
    const int tx = threadIdx.x & 31;
    const int ty = threadIdx.x >> 5;            // 0..7
    const int k0 = blockIdx.x * 32;
    const int n0 = blockIdx.y * 32;
#pragma unroll
    for (int i = 0; i < 4; i++)
        t[ty + i * 8][tx] = W[(size_t)(k0 + ty + i * 8) * DMODEL + n0 + tx];
    __syncthreads();
#pragma unroll
    for (int i = 0; i < 4; i++)
        out[(size_t)(n0 + ty + i * 8) * DMODEL + k0 + tx] = f2tf32f(t[tx][ty + i * 8]);
}

// =================================================================================
// tf32 mma.sync GEMM with cp.async double-buffering (flash r14's proven pattern).
// out = A[8192,512] * Bt^T + bias;  A and Bt both K-major, pre-RNA-rounded.
// Tile 128(M) x 128(N), K-chunk 16, 32 chunks. 256 thr = 8 warps (4M x 2N).
// smem: As/Bs [2][128*20] each; LD=20 words (80B rows: 16B-aligned for cp.async;
// 20*lr mod 32 = {0,20,8,28,16,4,24,12} -> all fragment reads conflict-free).
// Static smem total 40,960 B. MODE 0: head-major rounded g_Q/g_K/g_V; MODE 1: d_out.
// =================================================================================
#define TCM 128
#define TCN 128
#define TCK 16
#define NCHUNK (DMODEL / TCK)   // 32
#define LDT 20

__device__ __forceinline__ void gemm_load_chunk(unsigned abase, unsigned bbase,
                                                const float* __restrict__ Ab,
                                                const float* __restrict__ Bb, int tid)
{
    // each tile: 128 rows x 16 floats = 512 16B-chunks; 2 per thread per tile
#pragma unroll
    for (int i = 0; i < 2; i++) {
        const int e = i * 256 + tid;
        const int r = e >> 2, c = e & 3;
        cp_async16(abase + (unsigned)(r * LDT + c * 4) * 4u, Ab + (size_t)r * DMODEL + c * 4);
    }
#pragma unroll
    for (int i = 0; i < 2; i++) {
        const int e = i * 256 + tid;
        const int r = e >> 2, c = e & 3;
        cp_async16(bbase + (unsigned)(r * LDT + c * 4) * 4u, Bb + (size_t)r * DMODEL + c * 4);
    }
}

template <int MODE>
__global__ void __launch_bounds__(256)
gemm_ca_kernel(const float* __restrict__ bq, const float* __restrict__ bk,
               const float* __restrict__ bv, const float* __restrict__ bo,
               float* __restrict__ out_flat)
{
    __shared__ unsigned As[2][TCM * LDT];
    __shared__ unsigned Bs[2][TCN * LDT];

    const int tid  = threadIdx.x;
    const int lane = tid & 31;
    const int warp = tid >> 5;
    const int lr   = lane >> 2;   // 0..7
    const int lc   = lane & 3;    // 0..3
    const int warpM = warp >> 1;  // 0..3
    const int warpN = warp & 1;   // 0..1

    const int z = (MODE == 0) ? blockIdx.z : 3;
    const int rowBase = blockIdx.y * TCM;
    const int colBase = blockIdx.x * TCN;

    const float* A  = (MODE == 0) ? g_Xr : g_attn;
    const float* Bt = g_WT + (size_t)z * DMODEL * DMODEL;
    const float* bias = (MODE == 0) ? ((z == 0) ? bq : (z == 1) ? bk : bv) : bo;

    const float* Ab = A  + (size_t)rowBase * DMODEL;
    const float* Bb = Bt + (size_t)colBase * DMODEL;

    const unsigned aB0 = smem_u32(&As[0][0]), aB1 = smem_u32(&As[1][0]);
    const unsigned bB0 = smem_u32(&Bs[0][0]), bB1 = smem_u32(&Bs[1][0]);

    float acc[2][8][4];
#pragma unroll
    for (int mf = 0; mf < 2; mf++)
#pragma unroll
        for (int nf = 0; nf < 8; nf++)
#pragma unroll
            for (int c = 0; c < 4; c++) acc[mf][nf][c] = 0.0f;

    // prologue: chunk 0 -> buffer 0
    gemm_load_chunk(aB0, bB0, Ab, Bb, tid);
    cp_async_commit();

#pragma unroll 1
    for (int ch = 0; ch < NCHUNK; ch++) {
        const int buf = ch & 1;

        cp_async_wait_all();
        __syncthreads();   // chunk ch visible to all; other buffer fully consumed

        if (ch + 1 < NCHUNK) {   // prefetch next chunk into the other buffer
            gemm_load_chunk(buf ? aB0 : aB1, buf ? bB0 : bB1,
                            Ab + (ch + 1) * TCK, Bb + (ch + 1) * TCK, tid);
            cp_async_commit();
        }

#pragma unroll
        for (int ks = 0; ks < 2; ks++) {
            unsigned a[2][4];
#pragma unroll
            for (int mf = 0; mf < 2; mf++) {
                const int m0 = warpM * 32 + mf * 16;
                a[mf][0] = As[buf][(m0 + lr    ) * LDT + ks * 8 + lc];
                a[mf][1] = As[buf][(m0 + lr + 8) * LDT + ks * 8 + lc];
                a[mf][2] = As[buf][(m0 + lr    ) * LDT + ks * 8 + lc + 4];
                a[mf][3] = As[buf][(m0 + lr + 8) * LDT + ks * 8 + lc + 4];
            }
#pragma unroll
            for (int nf = 0; nf < 8; nf++) {
                const int n = warpN * 64 + nf * 8 + lr;
                const unsigned b0 = Bs[buf][n * LDT + ks * 8 + lc];
                const unsigned b1 = Bs[buf][n * LDT + ks * 8 + lc + 4];
                mma_tf32(acc[0][nf], a[0], b0, b1);
                mma_tf32(acc[1][nf], a[1], b0, b1);
            }
        }
    }

    // ---- epilogue: bias + store (r14-validated indexing) ------------------------
#pragma unroll
    for (int mf = 0; mf < 2; mf++) {
        const int r0 = rowBase + warpM * 32 + mf * 16 + lr;
        const int r1 = r0 + 8;
#pragma unroll
        for (int nf = 0; nf < 8; nf++) {
            const int col = colBase + warpN * 64 + nf * 8 + 2 * lc;
            const float2 bb = *reinterpret_cast<const float2*>(&bias[col]);
            float2 v0 = make_float2(acc[mf][nf][0] + bb.x, acc[mf][nf][1] + bb.y);
            float2 v1 = make_float2(acc[mf][nf][2] + bb.x, acc[mf][nf][3] + bb.y);
            if (MODE == 0) {
                v0.x = f2tf32f(v0.x); v0.y = f2tf32f(v0.y);
                v1.x = f2tf32f(v1.x); v1.y = f2tf32f(v1.y);
                float* outp = (z == 0) ? g_Q : (z == 1) ? g_K : g_V;
                const int h = col >> 6;
                const int d = col & 63;
                const int b0r = r0 >> 11, n0r = r0 & 2047;
                const int b1r = r1 >> 11, n1r = r1 & 2047;
                *reinterpret_cast<float2*>(
                    &outp[(((size_t)(b0r * NHEADS + h) * SEQ) + n0r) * DK + d]) = v0;
                *reinterpret_cast<float2*>(
                    &outp[(((size_t)(b1r * NHEADS + h) * SEQ) + n1r) * DK + d]) = v1;
            } else {
                *reinterpret_cast<float2*>(&out_flat[(size_t)r0 * DMODEL + col]) = v0;
                *reinterpret_cast<float2*>(&out_flat[(size_t)r1 * DMODEL + col]) = v1;
            }
        }
    }
}

// =================================================================================
// Flash attention (r14 exactly — 404us baseline's dominator, untouched) with one
// addition: epilogue RNA-rounds g_attn so the out-GEMM consumes raw bits.
// =================================================================================
#define FBQ 64
#define FBKV 32
#define LDK 68
#define LDV 72
#define LDP 36

__global__ void __launch_bounds__(128)
flash_kernel()
{
    __shared__ unsigned Ks[2][FBKV * LDK];
    __shared__ unsigned Vs[2][FBKV * LDV];
    __shared__ unsigned Ps[FBQ * LDP];

    const int tid  = threadIdx.x;
    const int lane = tid & 31;
    const int warp = tid >> 5;
    const int wrow = warp * 16;
    const int lr   = lane >> 2;
    const int lc   = lane & 3;

    const int q0 = blockIdx.x * FBQ;
    const int h  = blockIdx.y;
    const int b  = blockIdx.z;
    const size_t headBase = (size_t)(b * NHEADS + h) * SEQ * DK;
    const float scale = 0.125f;

    const unsigned ksBase0 = smem_u32(&Ks[0][0]);
    const unsigned ksBase1 = smem_u32(&Ks[1][0]);
    const unsigned vsBase0 = smem_u32(&Vs[0][0]);
    const unsigned vsBase1 = smem_u32(&Vs[1][0]);

    const float* Kg_head = g_K + headBase;
    const float* Vg_head = g_V + headBase;

    unsigned qf[8][4];
    {
        const float* Qg = g_Q + headBase + (size_t)(q0 + wrow) * DK;
#pragma unroll
        for (int ks = 0; ks < 8; ks++) {
            const int c0 = ks * 8 + lc;
            qf[ks][0] = f2tf32(Qg[(lr    ) * DK + c0    ] * scale);
            qf[ks][1] = f2tf32(Qg[(lr + 8) * DK + c0    ] * scale);
            qf[ks][2] = f2tf32(Qg[(lr    ) * DK + c0 + 4] * scale);
            qf[ks][3] = f2tf32(Qg[(lr + 8) * DK + c0 + 4] * scale);
        }
    }

    {
        const float* Kg = Kg_head;
        const float* Vg = Vg_head;
#pragma unroll
        for (int i = 0; i < 4; i++) {
            const int c = i * 128 + tid;
            const int row = c >> 4, ch = c & 15;
            cp_async16(ksBase0 + (unsigned)(row * LDK + ch * 4) * 4u, Kg + row * DK + ch * 4);
        }
#pragma unroll
        for (int i = 0; i < 4; i++) {
            const int c = i * 128 + tid;
            const int row = c >> 4, ch = c & 15;
            cp_async16(vsBase0 + (unsigned)(row * LDV + ch * 4) * 4u, Vg + row * DK + ch * 4);
        }
        cp_async_commit();
    }

    float m0 = -INFINITY, m1 = -INFINITY, l0 = 0.0f, l1 = 0.0f;
    float o[8][4];
#pragma unroll
    for (int nb = 0; nb < 8; nb++)
#pragma unroll
        for (int c = 0; c < 4; c++) o[nb][c] = 0.0f;

    for (int kt = 0; kt < SEQ / FBKV; kt++) {
        const int buf = kt & 1;

        cp_async_wait_all();
        __syncthreads();

        if (kt + 1 < SEQ / FBKV) {
            const float* Kg = Kg_head + (size_t)(kt + 1) * FBKV * DK;
            const float* Vg = Vg_head + (size_t)(kt + 1) * FBKV * DK;
            const unsigned kb = buf ? ksBase0 : ksBase1;
            const unsigned vb = buf ? vsBase0 : vsBase1;
#pragma unroll
            for (int i = 0; i < 4; i++) {
                const int c = i * 128 + tid;
                const int row = c >> 4, ch = c & 15;
                cp_async16(kb + (unsigned)(row * LDK + ch * 4) * 4u, Kg + row * DK + ch * 4);
            }
#pragma unroll
            for (int i = 0; i < 4; i++) {
                const int c = i * 128 + tid;
                const int row = c >> 4, ch = c & 15;
                cp_async16(vb + (unsigned)(row * LDV + ch * 4) * 4u, Vg + row * DK + ch * 4);
            }
            cp_async_commit();
        }

        float s[4][4];
#pragma unroll
        for (int nb = 0; nb < 4; nb++)
#pragma unroll
            for (int c = 0; c < 4; c++) s[nb][c] = 0.0f;

#pragma unroll
        for (int ks = 0; ks < 8; ks++) {
#pragma unroll
            for (int nb = 0; nb < 4; nb++) {
                const unsigned b0 = Ks[buf][(nb * 8 + lr) * LDK + ks * 8 + lc];
                const unsigned b1 = Ks[buf][(nb * 8 + lr) * LDK + ks * 8 + lc + 4];
                mma_tf32(s[nb], qf[ks], b0, b1);
            }
        }

#pragma unroll
        for (int hh = 0; hh < 2; hh++) {
            const int ci = hh * 2;
            float vmax = s[0][ci];
#pragma unroll
            for (int nb = 0; nb < 4; nb++)
                vmax = fmaxf(vmax, fmaxf(s[nb][ci], s[nb][ci + 1]));
            vmax = fmaxf(vmax, __shfl_xor_sync(0xffffffffu, vmax, 1));
            vmax = fmaxf(vmax, __shfl_xor_sync(0xffffffffu, vmax, 2));

            float& m = hh ? m1 : m0;
            float& l = hh ? l1 : l0;
            const float m_new = fmaxf(m, vmax);
            const float corr  = __expf(m - m_new);

            float sum = 0.0f;
            const int prow = wrow + lr + hh * 8;
#pragma unroll
            for (int nb = 0; nb < 4; nb++) {
                const float p0 = __expf(s[nb][ci]     - m_new);
                const float p1 = __expf(s[nb][ci + 1] - m_new);
                sum += p0 + p1;
                uint2 pp;
                pp.x = f2tf32(p0);
                pp.y = f2tf32(p1);
                *reinterpret_cast<uint2*>(&Ps[prow * LDP + nb * 8 + 2 * lc]) = pp;
            }
            sum += __shfl_xor_sync(0xffffffffu, sum, 1);
            sum += __shfl_xor_sync(0xffffffffu, sum, 2);

            l = l * corr + sum;
            m = m_new;
#pragma unroll
            for (int nb = 0; nb < 8; nb++) {
                o[nb][ci]     *= corr;
                o[nb][ci + 1] *= corr;
            }
        }
        __syncwarp();

#pragma unroll
        for (int ks = 0; ks < 4; ks++) {
            unsigned a[4];
            a[0] = Ps[(wrow + lr    ) * LDP + ks * 8 + lc];
            a[1] = Ps[(wrow + lr + 8) * LDP + ks * 8 + lc];
            a[2] = Ps[(wrow + lr    ) * LDP + ks * 8 + lc + 4];
            a[3] = Ps[(wrow + lr + 8) * LDP + ks * 8 + lc + 4];
#pragma unroll
            for (int nb = 0; nb < 8; nb++) {
                const unsigned b0 = Vs[buf][(ks * 8 + lc    ) * LDV + nb * 8 + lr];
                const unsigned b1 = Vs[buf][(ks * 8 + lc + 4) * LDV + nb * 8 + lr];
                mma_tf32(o[nb], a, b0, b1);
            }
        }
    }

    const float inv0 = 1.0f / l0;
    const float inv1 = 1.0f / l1;
    const int row0 = b * SEQ + q0 + wrow + lr;
    const int row1 = row0 + 8;
#pragma unroll
    for (int nb = 0; nb < 8; nb++) {
        const int col = h * DK + nb * 8 + 2 * lc;
        float2 w0 = make_float2(f2tf32f(o[nb][0] * inv0), f2tf32f(o[nb][1] * inv0));
        float2 w1 = make_float2(f2tf32f(o[nb][2] * inv1), f2tf32f(o[nb][3] * inv1));
        *reinterpret_cast<float2*>(&g_attn[(size_t)row0 * DMODEL + col]) = w0;
        *reinterpret_cast<float2*>(&g_attn[(size_t)row1 * DMODEL + col]) = w1;
    }
}

// =================================================================================
// launch
// =================================================================================
extern "C" void kernel_launch(void* const* d_in, const int* in_sizes, int n_in,
                              void* d_out, int out_size)
{
    const float* x  = (const float*)d_in[0];
    const float* Wq = (const float*)d_in[1];
    const float* bq = (const float*)d_in[2];
    const float* Wk = (const float*)d_in[3];
    const float* bk = (const float*)d_in[4];
    const float* Wv = (const float*)d_in[5];
    const float* bv = (const float*)d_in[6];
    const float* Wo = (const float*)d_in[7];
    const float* bo = (const float*)d_in[8];
    float* out = (float*)d_out;

    // 0) RNA-round inputs once (x and transposed weights)
    round_x_kernel<<<(MROWS * DMODEL / 4) / 256, 256>>>(x);
    transpose_round_kernel<<<dim3(16, 16, 4), 256>>>(Wq, Wk, Wv, Wo);

    // 1) QKV projections (tf32 mma.sync + cp.async) -> head-major rounded scratch
    gemm_ca_kernel<0><<<dim3(DMODEL / TCN, MROWS / TCM, 3), 256>>>(bq, bk, bv, bo, nullptr);

    // 2) flash attention (tf32 mma.sync, cp.async double-buffered) -> g_attn
    flash_kernel<<<dim3(SEQ / FBQ, NHEADS, BATCH), 128>>>();

    // 3) output projection -> d_out
    gemm_ca_kernel<1><<<dim3(DMODEL / TCN, MROWS / TCM, 1), 256>>>(bq, bk, bv, bo, out);
}